// round 1
// baseline (speedup 1.0000x reference)
#include <cuda_runtime.h>
#include <cuda_bf16.h>

// ============================================================================
// DQSN: x@w1'+b1 -> IF(16 steps) -> spikes@w2'+b2 -> LIF readout
//
// Collapse: out = A @ w2' + b2*(1 - 2^-16),
//   A[b,j] = sum_t spike_t(h_in[b,j]) * 2^(t-17),  h_in = x@w1' + b1
// A is exact in fp32 (sum of distinct powers of two in [2^-16, 2^-1]).
// GEMM1 epilogue runs the 16-step IF sim; GEMM2 applies the LIF-collapsed
// bias scale. Two TN-form fp32 SGEMMs (A,B both row-major, K contiguous).
// ============================================================================

namespace {
constexpr int BM = 128, BN = 128, BK = 16;
constexpr int TM = 8, TN = 8;
constexpr int THREADS = 256;           // 16 x 16 thread tile
constexpr int MDIM = 8192;
constexpr int IDIM = 256;              // K of gemm1
constexpr int HDIM = 1024;             // N of gemm1 / K of gemm2
constexpr int ODIM = 256;              // N of gemm2
}

// Scratch for A [8192, 1024] fp32 (32 MB). Static device array: no allocs.
__device__ float g_A[(size_t)MDIM * HDIM];

// C[m,n] = sum_k A[m*K+k] * B[n*K+k]  (+ epilogue)
// EPI=0: h = acc + bias[n]; 16-step IF sim -> A coefficient; store to C.
// EPI=1: C = acc + bias[n] * (1 - 2^-16)
template <int EPI>
__global__ __launch_bounds__(THREADS, 2)
void gemm_tn_kernel(const float* __restrict__ A, const float* __restrict__ B,
                    const float* __restrict__ bias, float* __restrict__ C,
                    int K, int N)
{
    __shared__ float As[BK][BM + 4];   // +4 pad: keeps 16B alignment, cuts conflicts
    __shared__ float Bs[BK][BN + 4];

    const int tid = threadIdx.x;
    const int tx = tid & 15;           // 0..15 -> N direction
    const int ty = tid >> 4;           // 0..15 -> M direction
    const int bm = blockIdx.y;
    const int bn = blockIdx.x;

    const float* Ab = A + (size_t)bm * BM * K;
    const float* Bb = B + (size_t)bn * BN * K;

    float acc[TM][TN];
#pragma unroll
    for (int i = 0; i < TM; i++)
#pragma unroll
        for (int j = 0; j < TN; j++) acc[i][j] = 0.0f;

    for (int k0 = 0; k0 < K; k0 += BK) {
        // Cooperative load: 128 rows x 16 k for each operand, transposed to
        // [k][row] layout in smem. 512 float4 per tile, 2 per thread.
#pragma unroll
        for (int r = 0; r < 2; r++) {
            const int lin = tid + r * THREADS;     // 0..511
            const int row = lin >> 2;              // 0..127
            const int kq  = (lin & 3) * 4;         // 0,4,8,12
            const float4 va =
                *reinterpret_cast<const float4*>(Ab + (size_t)row * K + k0 + kq);
            As[kq + 0][row] = va.x;
            As[kq + 1][row] = va.y;
            As[kq + 2][row] = va.z;
            As[kq + 3][row] = va.w;
            const float4 vb =
                *reinterpret_cast<const float4*>(Bb + (size_t)row * K + k0 + kq);
            Bs[kq + 0][row] = vb.x;
            Bs[kq + 1][row] = vb.y;
            Bs[kq + 2][row] = vb.z;
            Bs[kq + 3][row] = vb.w;
        }
        __syncthreads();

#pragma unroll
        for (int k = 0; k < BK; k++) {
            float a[TM], b[TN];
            const float4 a0 = *reinterpret_cast<const float4*>(&As[k][ty * TM]);
            const float4 a1 = *reinterpret_cast<const float4*>(&As[k][ty * TM + 4]);
            const float4 b0 = *reinterpret_cast<const float4*>(&Bs[k][tx * TN]);
            const float4 b1 = *reinterpret_cast<const float4*>(&Bs[k][tx * TN + 4]);
            a[0] = a0.x; a[1] = a0.y; a[2] = a0.z; a[3] = a0.w;
            a[4] = a1.x; a[5] = a1.y; a[6] = a1.z; a[7] = a1.w;
            b[0] = b0.x; b[1] = b0.y; b[2] = b0.z; b[3] = b0.w;
            b[4] = b1.x; b[5] = b1.y; b[6] = b1.z; b[7] = b1.w;
#pragma unroll
            for (int i = 0; i < TM; i++)
#pragma unroll
                for (int j = 0; j < TN; j++)
                    acc[i][j] = fmaf(a[i], b[j], acc[i][j]);
        }
        __syncthreads();
    }

    // Epilogue
#pragma unroll
    for (int i = 0; i < TM; i++) {
        const int rm = bm * BM + ty * TM + i;
#pragma unroll
        for (int j = 0; j < TN; j++) {
            const int cn = bn * BN + tx * TN + j;
            float val;
            if (EPI == 0) {
                // IF neuron, 16 steps, hard reset; accumulate LIF-weighted
                // spike coefficient A = sum_t s_t * 2^(t-17).
                const float h = acc[i][j] + bias[cn];
                float v = 0.0f, av = 0.0f, coef = 0x1p-16f;
#pragma unroll
                for (int t = 0; t < 16; t++) {
                    v += h;
                    const bool s = (v >= 1.0f);
                    av = s ? (av + coef) : av;
                    v  = s ? 0.0f : v;
                    coef += coef;
                }
                val = av;
            } else {
                val = acc[i][j] + bias[cn] * (1.0f - 0x1p-16f);
            }
            C[(size_t)rm * N + cn] = val;
        }
    }
}

extern "C" void kernel_launch(void* const* d_in, const int* in_sizes, int n_in,
                              void* d_out, int out_size)
{
    const float* x  = (const float*)d_in[0];   // [8192, 256]
    const float* w1 = (const float*)d_in[1];   // [1024, 256]
    const float* b1 = (const float*)d_in[2];   // [1024]
    const float* w2 = (const float*)d_in[3];   // [256, 1024]
    const float* b2 = (const float*)d_in[4];   // [256]
    float* out = (float*)d_out;                // [8192, 256]

    float* Aptr = nullptr;
    cudaGetSymbolAddress((void**)&Aptr, g_A);

    const dim3 blk(THREADS);
    // GEMM1 + IF sim: [8192,256] x [1024,256]' -> A [8192,1024]
    const dim3 g1(HDIM / BN, MDIM / BM);   // (8, 64)
    gemm_tn_kernel<0><<<g1, blk>>>(x, w1, b1, Aptr, IDIM, HDIM);
    // GEMM2: A [8192,1024] x [256,1024]' -> out [8192,256]
    const dim3 g2(ODIM / BN, MDIM / BM);   // (2, 64)
    gemm_tn_kernel<1><<<g2, blk>>>(Aptr, w2, b2, out, HDIM, ODIM);
}

// round 4
// speedup vs baseline: 1.2250x; 1.2250x over previous
#include <cuda_runtime.h>
#include <cuda_bf16.h>
#include <cstdint>

// ============================================================================
// DQSN collapsed: out = A @ w2' + b2*(1-2^-16)
//   A[b,j] = sum_t spike_t(h_in[b,j]) * 2^(t-17),  h_in = x@w1' + b1
// GEMM1 (x@w1'): tf32 mma.sync, K-tripled hi/lo split  (error ~7e-7, no flips)
// GEMM2 (A@w2'): bf16 mma.sync, K-tripled hi/lo split  (smooth, error ~1e-5)
// K-tripling: A'=[ah|ah|al], B'=[bh|bl|bh]  =>  ah*bh + ah*bl + al*bh
// ============================================================================

#define MDIM 8192
#define IDIM 256
#define HDIM 1024
#define ODIM 256

// --------------------------- global scratch (no allocs) ---------------------
__device__ __align__(16) float          g_x3 [(size_t)MDIM * (3 * IDIM)]; // [xh|xh|xl]
__device__ __align__(16) float          g_w13[(size_t)HDIM * (3 * IDIM)]; // [wh|wl|wh]
__device__ __align__(16) __nv_bfloat16  g_w23[(size_t)ODIM * (3 * HDIM)]; // [wh|wl|wh]
__device__ __align__(16) __nv_bfloat16  g_A3 [(size_t)MDIM * (3 * HDIM)]; // [Ah|Ah|Al]

// --------------------------- helpers ----------------------------------------
__device__ __forceinline__ uint32_t smem_addr_u32(const void* p) {
    return (uint32_t)__cvta_generic_to_shared(p);
}
__device__ __forceinline__ void cp16(uint32_t s, const void* g) {
    asm volatile("cp.async.cg.shared.global [%0], [%1], 16;" :: "r"(s), "l"(g));
}
#define CP_COMMIT() asm volatile("cp.async.commit_group;" ::: "memory")
#define CP_WAIT1()  asm volatile("cp.async.wait_group 1;" ::: "memory")

// cvt.rna.tf32.f32 takes a .b32 destination (tf32 = fp32 bit-pattern with
// truncated mantissa) -- bind to u32 and bit-cast back.
__device__ __forceinline__ float to_tf32(float x) {
    uint32_t r;
    asm("cvt.rna.tf32.f32 %0, %1;" : "=r"(r) : "f"(x));
    return __uint_as_float(r);
}
__device__ __forceinline__ uint32_t pack_bf(float a, float b) {
    __nv_bfloat162 t = __floats2bfloat162_rn(a, b);
    return *reinterpret_cast<uint32_t*>(&t);
}

__device__ __forceinline__ void mma_tf32(float* c, const uint32_t* a, const uint32_t* b) {
    asm volatile(
        "mma.sync.aligned.m16n8k8.row.col.f32.tf32.tf32.f32 "
        "{%0,%1,%2,%3}, {%4,%5,%6,%7}, {%8,%9}, {%0,%1,%2,%3};"
        : "+f"(c[0]), "+f"(c[1]), "+f"(c[2]), "+f"(c[3])
        : "r"(a[0]), "r"(a[1]), "r"(a[2]), "r"(a[3]), "r"(b[0]), "r"(b[1]));
}
__device__ __forceinline__ void mma_bf16(float* c, const uint32_t* a, const uint32_t* b) {
    asm volatile(
        "mma.sync.aligned.m16n8k16.row.col.f32.bf16.bf16.f32 "
        "{%0,%1,%2,%3}, {%4,%5,%6,%7}, {%8,%9}, {%0,%1,%2,%3};"
        : "+f"(c[0]), "+f"(c[1]), "+f"(c[2]), "+f"(c[3])
        : "r"(a[0]), "r"(a[1]), "r"(a[2]), "r"(a[3]), "r"(b[0]), "r"(b[1]));
}

// IF neuron closed-form sim (validated in R1, rel_err 4.4e-7)
__device__ __forceinline__ float if_sim(float h) {
    float v = 0.0f, av = 0.0f, coef = 0x1p-16f;
#pragma unroll
    for (int t = 0; t < 16; t++) {
        v += h;
        const bool s = (v >= 1.0f);
        av = s ? (av + coef) : av;
        v = s ? 0.0f : v;
        coef += coef;
    }
    return av;
}

// --------------------------- converters -------------------------------------
// tf32 hi/lo triple: ORDER 0 -> [h|h|l], ORDER 1 -> [h|l|h]
template <int ORDER>
__global__ __launch_bounds__(256)
void conv_tf32_kernel(const float* __restrict__ src, float* __restrict__ dst, int K)
{
    const int i = blockIdx.x * blockDim.x + threadIdx.x;  // pair index
    const int r = i / (K >> 1);
    const int c = (i - r * (K >> 1)) * 2;
    const float2 v = *reinterpret_cast<const float2*>(src + (size_t)r * K + c);
    const float h0 = to_tf32(v.x), h1 = to_tf32(v.y);
    const float l0 = to_tf32(v.x - h0), l1 = to_tf32(v.y - h1);
    float* d = dst + (size_t)r * (3 * K) + c;
    *reinterpret_cast<float2*>(d) = make_float2(h0, h1);
    if (ORDER == 0) {
        *reinterpret_cast<float2*>(d + K)     = make_float2(h0, h1);
        *reinterpret_cast<float2*>(d + 2 * K) = make_float2(l0, l1);
    } else {
        *reinterpret_cast<float2*>(d + K)     = make_float2(l0, l1);
        *reinterpret_cast<float2*>(d + 2 * K) = make_float2(h0, h1);
    }
}

// bf16 hi/lo triple, ORDER [h|l|h] (weights)
__global__ __launch_bounds__(256)
void conv_bf16_kernel(const float* __restrict__ src, __nv_bfloat16* __restrict__ dst, int K)
{
    const int i = blockIdx.x * blockDim.x + threadIdx.x;
    const int r = i / (K >> 1);
    const int c = (i - r * (K >> 1)) * 2;
    const float2 v = *reinterpret_cast<const float2*>(src + (size_t)r * K + c);
    const __nv_bfloat16 h0 = __float2bfloat16(v.x);
    const __nv_bfloat16 h1 = __float2bfloat16(v.y);
    const float l0 = v.x - __bfloat162float(h0);
    const float l1 = v.y - __bfloat162float(h1);
    const uint32_t hu = pack_bf(__bfloat162float(h0), __bfloat162float(h1));
    const uint32_t lu = pack_bf(l0, l1);
    uint32_t* d = reinterpret_cast<uint32_t*>(dst + (size_t)r * (3 * K) + c);
    d[0] = hu;
    d[K / 2] = lu;
    d[K] = hu;
}

// --------------------------- GEMM1: tf32, 128x128, BK=16 --------------------
// C = x3 @ w13'  (K'=768), epilogue: +b1, IF sim, write A3 = [Ah|Ah|Al] bf16.
#define G1_K3 768
#define G1_NK 48
#define G1_STRIDE 20                       // floats/row in smem (80B, conflict-free)
#define G1_STAGE ((128 + 128) * G1_STRIDE) // floats

__global__ __launch_bounds__(256, 2)
void gemm1_tf32(const float* __restrict__ Ag, const float* __restrict__ Bg,
                const float* __restrict__ bias, __nv_bfloat16* __restrict__ outA)
{
    __shared__ float sm[2 * G1_STAGE];     // 40960 B
    const uint32_t smb = smem_addr_u32(sm);

    const int tid = threadIdx.x;
    const int lane = tid & 31;
    const int wid = tid >> 5;
    const int g = lane >> 2, t = lane & 3;
    const int wm = (wid & 1) * 64, wn = (wid >> 1) * 32;
    const int mblk = blockIdx.y, nblk = blockIdx.x;

    float acc[4][4][4];
#pragma unroll
    for (int i = 0; i < 4; i++)
#pragma unroll
        for (int j = 0; j < 4; j++)
#pragma unroll
            for (int k = 0; k < 4; k++) acc[i][j][k] = 0.0f;

    // stage loader: 1024 16B-chunks, 4 per thread
    auto load_stage = [&](int s, int kt) {
        const int k0 = kt * 16;
#pragma unroll
        for (int i = 0; i < 4; i++) {
            const int c = tid + i * 256;
            const int row = c >> 2, ch = (c & 3) * 4;
            const float* gp;
            if (row < 128)
                gp = Ag + (size_t)(mblk * 128 + row) * G1_K3 + k0 + ch;
            else
                gp = Bg + (size_t)(nblk * 128 + (row - 128)) * G1_K3 + k0 + ch;
            cp16(smb + (uint32_t)(s * G1_STAGE + row * G1_STRIDE + ch) * 4, gp);
        }
    };

    load_stage(0, 0);
    CP_COMMIT();
    for (int kt = 0; kt < G1_NK; kt++) {
        if (kt + 1 < G1_NK) load_stage((kt + 1) & 1, kt + 1);
        CP_COMMIT();
        CP_WAIT1();
        __syncthreads();
        const float* As = sm + (kt & 1) * G1_STAGE;
        const float* Bs = As + 128 * G1_STRIDE;
#pragma unroll
        for (int kk = 0; kk < 16; kk += 8) {
            uint32_t a[4][4], b[4][2];
#pragma unroll
            for (int ma = 0; ma < 4; ma++) {
                const uint32_t* ap =
                    reinterpret_cast<const uint32_t*>(As + (wm + ma * 16 + g) * G1_STRIDE + kk);
                const uint32_t* ap8 =
                    reinterpret_cast<const uint32_t*>(As + (wm + ma * 16 + g + 8) * G1_STRIDE + kk);
                a[ma][0] = ap[t];
                a[ma][1] = ap8[t];
                a[ma][2] = ap[t + 4];
                a[ma][3] = ap8[t + 4];
            }
#pragma unroll
            for (int na = 0; na < 4; na++) {
                const uint32_t* bp =
                    reinterpret_cast<const uint32_t*>(Bs + (wn + na * 8 + g) * G1_STRIDE + kk);
                b[na][0] = bp[t];
                b[na][1] = bp[t + 4];
            }
#pragma unroll
            for (int ma = 0; ma < 4; ma++)
#pragma unroll
                for (int na = 0; na < 4; na++) mma_tf32(acc[ma][na], a[ma], b[na]);
        }
        __syncthreads();
    }

    // epilogue: +bias, IF sim, exact bf16 hi/lo split of A, tripled write
#pragma unroll
    for (int na = 0; na < 4; na++) {
        const int col = nblk * 128 + wn + na * 8 + 2 * t;
        const float bb0 = __ldg(bias + col);
        const float bb1 = __ldg(bias + col + 1);
#pragma unroll
        for (int ma = 0; ma < 4; ma++) {
            const int row0 = mblk * 128 + wm + ma * 16 + g;
#pragma unroll
            for (int rv = 0; rv < 2; rv++) {
                const int row = row0 + rv * 8;
                const float a0 = if_sim(acc[ma][na][rv * 2 + 0] + bb0);
                const float a1 = if_sim(acc[ma][na][rv * 2 + 1] + bb1);
                const __nv_bfloat16 h0 = __float2bfloat16(a0);
                const __nv_bfloat16 h1 = __float2bfloat16(a1);
                const uint32_t hu = pack_bf(a0, a1);   // A fits 16 dyadic bits,
                const uint32_t lu = pack_bf(a0 - __bfloat162float(h0),
                                            a1 - __bfloat162float(h1)); // split exact
                uint32_t* d = reinterpret_cast<uint32_t*>(
                    outA + (size_t)row * (3 * HDIM) + col);
                d[0] = hu;
                d[HDIM / 2] = hu;
                d[HDIM] = lu;
            }
        }
    }
}

// --------------------------- GEMM2: bf16, 128x64, BK=32 ---------------------
// out = A3 @ w23' (K'=3072), epilogue: + b2*(1-2^-16), fp32 row-major [., 256]
#define G2_K3 3072
#define G2_NK 96
#define G2_STRIDE 40                        // halves/row (80B, conflict-free)
#define G2_STAGE ((128 + 64) * G2_STRIDE)   // halves

__global__ __launch_bounds__(256, 2)
void gemm2_bf16(const __nv_bfloat16* __restrict__ Ag, const __nv_bfloat16* __restrict__ Bg,
                const float* __restrict__ bias, float* __restrict__ out)
{
    __shared__ __nv_bfloat16 sm[2 * G2_STAGE];   // 30720 B
    const uint32_t smb = smem_addr_u32(sm);

    const int tid = threadIdx.x;
    const int lane = tid & 31;
    const int wid = tid >> 5;
    const int g = lane >> 2, t = lane & 3;
    const int wm = (wid & 1) * 64, wn = (wid >> 1) * 16;
    const int mblk = blockIdx.y, nblk = blockIdx.x;

    float acc[4][2][4];
#pragma unroll
    for (int i = 0; i < 4; i++)
#pragma unroll
        for (int j = 0; j < 2; j++)
#pragma unroll
            for (int k = 0; k < 4; k++) acc[i][j][k] = 0.0f;

    // 768 16B-chunks per stage, 3 per thread
    auto load_stage = [&](int s, int kt) {
        const int k0 = kt * 32;
#pragma unroll
        for (int i = 0; i < 3; i++) {
            const int c = tid + i * 256;
            const int row = c >> 2, ch = (c & 3) * 8;  // halves
            const __nv_bfloat16* gp;
            if (row < 128)
                gp = Ag + (size_t)(mblk * 128 + row) * G2_K3 + k0 + ch;
            else
                gp = Bg + (size_t)(nblk * 64 + (row - 128)) * G2_K3 + k0 + ch;
            cp16(smb + (uint32_t)(s * G2_STAGE + row * G2_STRIDE + ch) * 2, gp);
        }
    };

    load_stage(0, 0);
    CP_COMMIT();
    for (int kt = 0; kt < G2_NK; kt++) {
        if (kt + 1 < G2_NK) load_stage((kt + 1) & 1, kt + 1);
        CP_COMMIT();
        CP_WAIT1();
        __syncthreads();
        const __nv_bfloat16* As = sm + (kt & 1) * G2_STAGE;
        const __nv_bfloat16* Bs = As + 128 * G2_STRIDE;
#pragma unroll
        for (int kk = 0; kk < 32; kk += 16) {
            uint32_t a[4][4], b[2][2];
#pragma unroll
            for (int ma = 0; ma < 4; ma++) {
                const __nv_bfloat16* r0 = As + (wm + ma * 16 + g) * G2_STRIDE + kk + 2 * t;
                const __nv_bfloat16* r8 = As + (wm + ma * 16 + g + 8) * G2_STRIDE + kk + 2 * t;
                a[ma][0] = *reinterpret_cast<const uint32_t*>(r0);
                a[ma][1] = *reinterpret_cast<const uint32_t*>(r8);
                a[ma][2] = *reinterpret_cast<const uint32_t*>(r0 + 8);
                a[ma][3] = *reinterpret_cast<const uint32_t*>(r8 + 8);
            }
#pragma unroll
            for (int na = 0; na < 2; na++) {
                const __nv_bfloat16* bp = Bs + (wn + na * 8 + g) * G2_STRIDE + kk + 2 * t;
                b[na][0] = *reinterpret_cast<const uint32_t*>(bp);
                b[na][1] = *reinterpret_cast<const uint32_t*>(bp + 8);
            }
#pragma unroll
            for (int ma = 0; ma < 4; ma++)
#pragma unroll
                for (int na = 0; na < 2; na++) mma_bf16(acc[ma][na], a[ma], b[na]);
        }
        __syncthreads();
    }

    const float BSCALE = 1.0f - 0x1p-16f;
#pragma unroll
    for (int na = 0; na < 2; na++) {
        const int col = nblk * 64 + wn + na * 8 + 2 * t;
        const float bb0 = __ldg(bias + col) * BSCALE;
        const float bb1 = __ldg(bias + col + 1) * BSCALE;
#pragma unroll
        for (int ma = 0; ma < 4; ma++) {
            const int row0 = mblk * 128 + wm + ma * 16 + g;
            *reinterpret_cast<float2*>(out + (size_t)row0 * ODIM + col) =
                make_float2(acc[ma][na][0] + bb0, acc[ma][na][1] + bb1);
            *reinterpret_cast<float2*>(out + (size_t)(row0 + 8) * ODIM + col) =
                make_float2(acc[ma][na][2] + bb0, acc[ma][na][3] + bb1);
        }
    }
}

// --------------------------- launch -----------------------------------------
extern "C" void kernel_launch(void* const* d_in, const int* in_sizes, int n_in,
                              void* d_out, int out_size)
{
    const float* x  = (const float*)d_in[0];   // [8192, 256]
    const float* w1 = (const float*)d_in[1];   // [1024, 256]
    const float* b1 = (const float*)d_in[2];   // [1024]
    const float* w2 = (const float*)d_in[3];   // [256, 1024]
    const float* b2 = (const float*)d_in[4];   // [256]
    float* out = (float*)d_out;                // [8192, 256]

    float *x3, *w13;
    __nv_bfloat16 *w23, *A3;
    cudaGetSymbolAddress((void**)&x3,  g_x3);
    cudaGetSymbolAddress((void**)&w13, g_w13);
    cudaGetSymbolAddress((void**)&w23, g_w23);
    cudaGetSymbolAddress((void**)&A3,  g_A3);

    conv_tf32_kernel<0><<<MDIM * IDIM / 2 / 256, 256>>>(x,  x3,  IDIM);
    conv_tf32_kernel<1><<<HDIM * IDIM / 2 / 256, 256>>>(w1, w13, IDIM);
    conv_bf16_kernel<<<ODIM * HDIM / 2 / 256, 256>>>(w2, w23, HDIM);

    gemm1_tf32<<<dim3(HDIM / 128, MDIM / 128), 256>>>(x3, w13, b1, A3);
    gemm2_bf16<<<dim3(ODIM / 64, MDIM / 128), 256>>>(A3, w23, b2, out);
}

// round 5
// speedup vs baseline: 1.5566x; 1.2707x over previous
#include <cuda_runtime.h>
#include <cuda_fp16.h>
#include <cstdint>

// ============================================================================
// DQSN collapsed: out = A @ w2' + b2*(1-2^-16)
//   A[b,j] = sum_t spike_t(h_in[b,j]) * 2^(t-17),  h_in = x@w1' + b1
// GEMM1: fp16 mma, K-quadrupled split [x1|x1|x2|x2]x[w1|w2|w1|w2] (err ~1e-7)
// GEMM2: fp16 mma, K-tripled split [Ah|Ah|Al]x[wh|wl|wh]  (A split exact)
// Fragments via ldmatrix.x4 (R4 was MIO-bound on scalar LDS: issue=32%).
// ============================================================================

#define MDIM 8192
#define IDIM 256
#define HDIM 1024
#define ODIM 256

#define G1_K3 1024          // 4 * IDIM
#define G1_NK 32
#define G2_K3 3072          // 3 * HDIM
#define G2_NK 96
#define STRIDE 40           // halves per smem row (80B, ldmatrix conflict-free)

// --------------------------- global scratch (no allocs) ---------------------
__device__ __align__(16) __half g_x4 [(size_t)MDIM * G1_K3];  // [x1|x1|x2|x2]
__device__ __align__(16) __half g_w14[(size_t)HDIM * G1_K3];  // [wh|wl|wh|wl]
__device__ __align__(16) __half g_w23[(size_t)ODIM * G2_K3];  // [wh|wl|wh]
__device__ __align__(16) __half g_A3 [(size_t)MDIM * G2_K3];  // [Ah|Ah|Al]

// --------------------------- helpers ----------------------------------------
__device__ __forceinline__ uint32_t smem_addr_u32(const void* p) {
    return (uint32_t)__cvta_generic_to_shared(p);
}
__device__ __forceinline__ void cp16(uint32_t s, const void* g) {
    asm volatile("cp.async.cg.shared.global [%0], [%1], 16;" :: "r"(s), "l"(g));
}
#define CP_COMMIT() asm volatile("cp.async.commit_group;" ::: "memory")
#define CP_WAIT1()  asm volatile("cp.async.wait_group 1;" ::: "memory")

__device__ __forceinline__ void ldm_x4(uint32_t* r, uint32_t addr) {
    asm volatile("ldmatrix.sync.aligned.m8n8.x4.shared.b16 {%0,%1,%2,%3}, [%4];"
        : "=r"(r[0]), "=r"(r[1]), "=r"(r[2]), "=r"(r[3]) : "r"(addr));
}
__device__ __forceinline__ void mma_f16(float* c, const uint32_t* a, const uint32_t* b) {
    asm volatile(
        "mma.sync.aligned.m16n8k16.row.col.f32.f16.f16.f32 "
        "{%0,%1,%2,%3}, {%4,%5,%6,%7}, {%8,%9}, {%0,%1,%2,%3};"
        : "+f"(c[0]), "+f"(c[1]), "+f"(c[2]), "+f"(c[3])
        : "r"(a[0]), "r"(a[1]), "r"(a[2]), "r"(a[3]), "r"(b[0]), "r"(b[1]));
}
__device__ __forceinline__ uint32_t pack_h2(float a, float b) {
    __half2 t = __floats2half2_rn(a, b);
    return *reinterpret_cast<uint32_t*>(&t);
}

// IF neuron closed-form sim (validated in R1, rel_err 4.4e-7)
__device__ __forceinline__ float if_sim(float h) {
    float v = 0.0f, av = 0.0f, coef = 0x1p-16f;
#pragma unroll
    for (int t = 0; t < 16; t++) {
        v += h;
        const bool s = (v >= 1.0f);
        av = s ? (av + coef) : av;
        v = s ? 0.0f : v;
        coef += coef;
    }
    return av;
}

// --------------------------- converters -------------------------------------
// fp16 hi/lo quad: ORDER 0 -> [h|h|l|l] (x), ORDER 1 -> [h|l|h|l] (w1)
template <int ORDER>
__global__ __launch_bounds__(256)
void conv_quad_kernel(const float* __restrict__ src, __half* __restrict__ dst, int K)
{
    const int i = blockIdx.x * blockDim.x + threadIdx.x;  // pair index
    const int r = i / (K >> 1);
    const int c = (i - r * (K >> 1)) * 2;
    const float2 v = *reinterpret_cast<const float2*>(src + (size_t)r * K + c);
    const __half h0 = __float2half_rn(v.x);
    const __half h1 = __float2half_rn(v.y);
    const float l0 = v.x - __half2float(h0);
    const float l1 = v.y - __half2float(h1);
    const uint32_t hu = pack_h2(__half2float(h0), __half2float(h1));
    const uint32_t lu = pack_h2(l0, l1);
    uint32_t* d = reinterpret_cast<uint32_t*>(dst + (size_t)r * (4 * K) + c);
    const int Kh = K >> 1;
    if (ORDER == 0) {
        d[0] = hu; d[Kh] = hu; d[2 * Kh] = lu; d[3 * Kh] = lu;
    } else {
        d[0] = hu; d[Kh] = lu; d[2 * Kh] = hu; d[3 * Kh] = lu;
    }
}

// fp16 hi/lo triple [h|l|h] for w2
__global__ __launch_bounds__(256)
void conv_tri_kernel(const float* __restrict__ src, __half* __restrict__ dst, int K)
{
    const int i = blockIdx.x * blockDim.x + threadIdx.x;
    const int r = i / (K >> 1);
    const int c = (i - r * (K >> 1)) * 2;
    const float2 v = *reinterpret_cast<const float2*>(src + (size_t)r * K + c);
    const __half h0 = __float2half_rn(v.x);
    const __half h1 = __float2half_rn(v.y);
    const float l0 = v.x - __half2float(h0);
    const float l1 = v.y - __half2float(h1);
    const uint32_t hu = pack_h2(__half2float(h0), __half2float(h1));
    const uint32_t lu = pack_h2(l0, l1);
    uint32_t* d = reinterpret_cast<uint32_t*>(dst + (size_t)r * (3 * K) + c);
    const int Kh = K >> 1;
    d[0] = hu; d[Kh] = lu; d[2 * Kh] = hu;
}

// --------------------------- GEMM1: fp16, 128x128, BK=32 --------------------
// C = x4 @ w14' (K'=1024), epilogue: +b1, IF sim, write A3=[Ah|Ah|Al] fp16.
#define G1_STAGE (256 * STRIDE)   // halves

__global__ __launch_bounds__(256, 2)
void gemm1_f16(const __half* __restrict__ Ag, const __half* __restrict__ Bg,
               const float* __restrict__ bias, __half* __restrict__ outA)
{
    __shared__ __half sm[2 * G1_STAGE];   // 40960 B
    const uint32_t smb = smem_addr_u32(sm);

    const int tid = threadIdx.x;
    const int lane = tid & 31;
    const int wid = tid >> 5;
    const int g = lane >> 3, lr = lane & 7;
    const int wm = (wid & 1) * 64, wn = (wid >> 1) * 32;
    const int mblk = blockIdx.y, nblk = blockIdx.x;

    // ldmatrix row offsets (halves, relative to stage base)
    int a_off[4], b_off[2];
#pragma unroll
    for (int ma = 0; ma < 4; ma++)
        a_off[ma] = (wm + ma * 16 + (g & 1) * 8 + lr) * STRIDE + (g >> 1) * 8;
#pragma unroll
    for (int nb = 0; nb < 2; nb++)
        b_off[nb] = (128 + wn + nb * 16 + (g >> 1) * 8 + lr) * STRIDE + (g & 1) * 8;

    float acc[4][4][4];
#pragma unroll
    for (int i = 0; i < 4; i++)
#pragma unroll
        for (int j = 0; j < 4; j++)
#pragma unroll
            for (int k = 0; k < 4; k++) acc[i][j][k] = 0.0f;

    // stage loader: 1024 16B-chunks, 4 per thread
    auto load_stage = [&](int s, int kt) {
        const int k0 = kt * 32;
#pragma unroll
        for (int i = 0; i < 4; i++) {
            const int c = tid + i * 256;
            const int row = c >> 2, ch = (c & 3) * 8;   // halves
            const __half* gp;
            if (row < 128)
                gp = Ag + (size_t)(mblk * 128 + row) * G1_K3 + k0 + ch;
            else
                gp = Bg + (size_t)(nblk * 128 + (row - 128)) * G1_K3 + k0 + ch;
            cp16(smb + (uint32_t)(s * G1_STAGE + row * STRIDE + ch) * 2, gp);
        }
    };

    load_stage(0, 0);
    CP_COMMIT();
    for (int kt = 0; kt < G1_NK; kt++) {
        if (kt + 1 < G1_NK) load_stage((kt + 1) & 1, kt + 1);
        CP_COMMIT();
        CP_WAIT1();
        __syncthreads();
        const uint32_t stg = smb + (uint32_t)((kt & 1) * G1_STAGE) * 2;
#pragma unroll
        for (int kk = 0; kk < 32; kk += 16) {
            uint32_t a[4][4], b[4][2];
#pragma unroll
            for (int ma = 0; ma < 4; ma++)
                ldm_x4(a[ma], stg + (uint32_t)(a_off[ma] + kk) * 2);
#pragma unroll
            for (int nb = 0; nb < 2; nb++) {
                uint32_t r[4];
                ldm_x4(r, stg + (uint32_t)(b_off[nb] + kk) * 2);
                b[2 * nb][0] = r[0]; b[2 * nb][1] = r[1];
                b[2 * nb + 1][0] = r[2]; b[2 * nb + 1][1] = r[3];
            }
#pragma unroll
            for (int ma = 0; ma < 4; ma++)
#pragma unroll
                for (int na = 0; na < 4; na++) mma_f16(acc[ma][na], a[ma], b[na]);
        }
        __syncthreads();
    }

    // epilogue: +bias, IF sim, exact fp16 hi/lo split of A, tripled write
    const int gq = lane >> 2, tq = lane & 3;
#pragma unroll
    for (int na = 0; na < 4; na++) {
        const int col = nblk * 128 + wn + na * 8 + 2 * tq;
        const float bb0 = __ldg(bias + col);
        const float bb1 = __ldg(bias + col + 1);
#pragma unroll
        for (int ma = 0; ma < 4; ma++) {
            const int row0 = mblk * 128 + wm + ma * 16 + gq;
#pragma unroll
            for (int rv = 0; rv < 2; rv++) {
                const int row = row0 + rv * 8;
                const float a0 = if_sim(acc[ma][na][rv * 2 + 0] + bb0);
                const float a1 = if_sim(acc[ma][na][rv * 2 + 1] + bb1);
                const __half h0 = __float2half_rn(a0);   // A has 16 dyadic bits:
                const __half h1 = __float2half_rn(a1);   // fp16 split is EXACT
                const uint32_t hu = pack_h2(a0, a1);
                const uint32_t lu = pack_h2(a0 - __half2float(h0),
                                            a1 - __half2float(h1));
                uint32_t* d = reinterpret_cast<uint32_t*>(
                    outA + (size_t)row * G2_K3 + col);
                d[0] = hu;
                d[HDIM / 2] = hu;
                d[HDIM] = lu;
            }
        }
    }
}

// --------------------------- GEMM2: fp16, 128x64, BK=32 ---------------------
// out = A3 @ w23' (K'=3072), epilogue: + b2*(1-2^-16), fp32 row-major [., 256]
#define G2_STAGE (192 * STRIDE)   // halves

__global__ __launch_bounds__(256, 2)
void gemm2_f16(const __half* __restrict__ Ag, const __half* __restrict__ Bg,
               const float* __restrict__ bias, float* __restrict__ out)
{
    __shared__ __half sm[2 * G2_STAGE];   // 30720 B
    const uint32_t smb = smem_addr_u32(sm);

    const int tid = threadIdx.x;
    const int lane = tid & 31;
    const int wid = tid >> 5;
    const int g = lane >> 3, lr = lane & 7;
    const int wm = (wid & 1) * 64, wn = (wid >> 1) * 16;
    const int mblk = blockIdx.y, nblk = blockIdx.x;

    int a_off[4], b_off;
#pragma unroll
    for (int ma = 0; ma < 4; ma++)
        a_off[ma] = (wm + ma * 16 + (g & 1) * 8 + lr) * STRIDE + (g >> 1) * 8;
    b_off = (128 + wn + (g >> 1) * 8 + lr) * STRIDE + (g & 1) * 8;

    float acc[4][2][4];
#pragma unroll
    for (int i = 0; i < 4; i++)
#pragma unroll
        for (int j = 0; j < 2; j++)
#pragma unroll
            for (int k = 0; k < 4; k++) acc[i][j][k] = 0.0f;

    // 768 16B-chunks per stage, 3 per thread
    auto load_stage = [&](int s, int kt) {
        const int k0 = kt * 32;
#pragma unroll
        for (int i = 0; i < 3; i++) {
            const int c = tid + i * 256;
            const int row = c >> 2, ch = (c & 3) * 8;
            const __half* gp;
            if (row < 128)
                gp = Ag + (size_t)(mblk * 128 + row) * G2_K3 + k0 + ch;
            else
                gp = Bg + (size_t)(nblk * 64 + (row - 128)) * G2_K3 + k0 + ch;
            cp16(smb + (uint32_t)(s * G2_STAGE + row * STRIDE + ch) * 2, gp);
        }
    };

    load_stage(0, 0);
    CP_COMMIT();
    for (int kt = 0; kt < G2_NK; kt++) {
        if (kt + 1 < G2_NK) load_stage((kt + 1) & 1, kt + 1);
        CP_COMMIT();
        CP_WAIT1();
        __syncthreads();
        const uint32_t stg = smb + (uint32_t)((kt & 1) * G2_STAGE) * 2;
#pragma unroll
        for (int kk = 0; kk < 32; kk += 16) {
            uint32_t a[4][4], b[2][2];
#pragma unroll
            for (int ma = 0; ma < 4; ma++)
                ldm_x4(a[ma], stg + (uint32_t)(a_off[ma] + kk) * 2);
            {
                uint32_t r[4];
                ldm_x4(r, stg + (uint32_t)(b_off + kk) * 2);
                b[0][0] = r[0]; b[0][1] = r[1];
                b[1][0] = r[2]; b[1][1] = r[3];
            }
#pragma unroll
            for (int ma = 0; ma < 4; ma++)
#pragma unroll
                for (int na = 0; na < 2; na++) mma_f16(acc[ma][na], a[ma], b[na]);
        }
        __syncthreads();
    }

    const float BSCALE = 1.0f - 0x1p-16f;
    const int gq = lane >> 2, tq = lane & 3;
#pragma unroll
    for (int na = 0; na < 2; na++) {
        const int col = nblk * 64 + wn + na * 8 + 2 * tq;
        const float bb0 = __ldg(bias + col) * BSCALE;
        const float bb1 = __ldg(bias + col + 1) * BSCALE;
#pragma unroll
        for (int ma = 0; ma < 4; ma++) {
            const int row0 = mblk * 128 + wm + ma * 16 + gq;
            *reinterpret_cast<float2*>(out + (size_t)row0 * ODIM + col) =
                make_float2(acc[ma][na][0] + bb0, acc[ma][na][1] + bb1);
            *reinterpret_cast<float2*>(out + (size_t)(row0 + 8) * ODIM + col) =
                make_float2(acc[ma][na][2] + bb0, acc[ma][na][3] + bb1);
        }
    }
}

// --------------------------- launch -----------------------------------------
extern "C" void kernel_launch(void* const* d_in, const int* in_sizes, int n_in,
                              void* d_out, int out_size)
{
    const float* x  = (const float*)d_in[0];   // [8192, 256]
    const float* w1 = (const float*)d_in[1];   // [1024, 256]
    const float* b1 = (const float*)d_in[2];   // [1024]
    const float* w2 = (const float*)d_in[3];   // [256, 1024]
    const float* b2 = (const float*)d_in[4];   // [256]
    float* out = (float*)d_out;                // [8192, 256]

    __half *x4, *w14, *w23, *A3;
    cudaGetSymbolAddress((void**)&x4,  g_x4);
    cudaGetSymbolAddress((void**)&w14, g_w14);
    cudaGetSymbolAddress((void**)&w23, g_w23);
    cudaGetSymbolAddress((void**)&A3,  g_A3);

    conv_quad_kernel<0><<<MDIM * IDIM / 2 / 256, 256>>>(x,  x4,  IDIM);
    conv_quad_kernel<1><<<HDIM * IDIM / 2 / 256, 256>>>(w1, w14, IDIM);
    conv_tri_kernel<<<ODIM * HDIM / 2 / 256, 256>>>(w2, w23, HDIM);

    gemm1_f16<<<dim3(HDIM / 128, MDIM / 128), 256>>>(x4, w14, b1, A3);
    gemm2_f16<<<dim3(ODIM / 64, MDIM / 128), 256>>>(A3, w23, b2, out);
}